// round 5
// baseline (speedup 1.0000x reference)
#include <cuda_runtime.h>

#define LDIM  8192
#define FDIM  100
#define SEG   512         // positions per CTA
#define SEGS  16
#define BROWS 64
#define PW    20          // words per bitplane (max used index 19)
#define VP    65          // 64 vocab planes + always-zero plane for PAD
#define NTHREADS 128
#define NG    160         // int4 token groups per CTA (tokens 0..639)

// cross-CTA combine scratch (zero at load; reset by finalizer each launch)
__device__ unsigned long long g_key[BROWS];
__device__ unsigned int       g_cnt[BROWS];

__device__ __forceinline__ unsigned IND(const unsigned* __restrict__ pl,
                                        const int* __restrict__ soff,
                                        int f, int blk)
{
    const unsigned* p = pl + soff[f] + blk + (f >> 5);
    return __funnelshift_r(p[0], p[1], f & 31);
}

__device__ __forceinline__ unsigned MAJ(unsigned a, unsigned b, unsigned c) {
    return (a & b) | (a & c) | (b & c);   // single LOP3
}

// accumulate NF f's starting at fb over 32 positions of block blk (two chains for ILP)
template<int NF>
__device__ __forceinline__ void accum(const unsigned* __restrict__ pl,
                                      const int* __restrict__ soff,
                                      int fb, int blk, unsigned cnt[4])
{
    constexpr int H0 = NF / 2, H1 = NF - H0;   // each half <= 7 -> 3 planes
    unsigned o0 = 0, t0 = 0, q0 = 0;
    unsigned o1 = 0, t1 = 0, q1 = 0;
    #pragma unroll
    for (int j = 0; j < H1; j++) {
        if (j < H0) {
            unsigned x = IND(pl, soff, fb + j, blk);
            unsigned c = o0 & x; o0 ^= x;
            unsigned d = t0 & c; t0 ^= c;
            q0 |= d;
        }
        {
            unsigned x = IND(pl, soff, fb + H0 + j, blk);
            unsigned c = o1 & x; o1 ^= x;
            unsigned d = t1 & c; t1 ^= c;
            q1 |= d;
        }
    }
    unsigned c0 = o0 & o1;            cnt[0] = o0 ^ o1;
    unsigned c1 = MAJ(t0, t1, c0);    cnt[1] = t0 ^ t1 ^ c0;
    unsigned c2 = MAJ(q0, q1, c1);    cnt[2] = q0 ^ q1 ^ c1;
    cnt[3] = c2;                      // NF <= 13 -> sum <= 13 < 16
}

__global__ __launch_bounds__(NTHREADS)
void finder_kernel(const int* __restrict__ expr,
                   const int* __restrict__ sub,
                   float* __restrict__ out, int B)
{
    __shared__ unsigned planes[VP * PW];   // 5.2 KB bitboards
    __shared__ int soff[FDIM];
    __shared__ unsigned long long wkey[NTHREADS / 32];

    const int s   = blockIdx.x;            // segment 0..15
    const int b   = blockIdx.y;            // batch row
    const int tid = threadIdx.x;
    const int p0  = s * SEG;

    // ---- prefetch gmem (overlaps shared zeroing) ----
    const int* erow = expr + b * LDIM;
    int4 v0, v1;
    bool h0 = false, h1 = false;
    {
        int tg = p0 + 4 * tid;
        if (tg < LDIM) { v0 = *(const int4*)(erow + tg); h0 = true; }
        tg = p0 + 4 * (tid + NTHREADS);
        if (tid + NTHREADS < NG && tg < LDIM) { v1 = *(const int4*)(erow + tg); h1 = true; }
    }
    int sval = 0;
    if (tid < FDIM) sval = sub[b * FDIM + tid];

    // ---- zero bitplanes: 1300 words = 325 uint4 ----
    for (int i = tid; i < VP * PW / 4; i += NTHREADS)
        ((uint4*)planes)[i] = make_uint4(0, 0, 0, 0);
    if (tid < FDIM) soff[tid] = (sval == 0 ? 64 : sval) * PW;  // PAD -> zero plane
    __syncthreads();

    // ---- scatter bitboard bits ----
    if (h0) {
        const int tl = 4 * tid, w = tl >> 5;
        atomicOr(&planes[v0.x * PW + w], 1u << ((tl    ) & 31));
        atomicOr(&planes[v0.y * PW + w], 1u << ((tl + 1) & 31));
        atomicOr(&planes[v0.z * PW + w], 1u << ((tl + 2) & 31));
        atomicOr(&planes[v0.w * PW + w], 1u << ((tl + 3) & 31));
    }
    if (h1) {
        const int tl = 4 * (tid + NTHREADS), w = tl >> 5;
        atomicOr(&planes[v1.x * PW + w], 1u << ((tl    ) & 31));
        atomicOr(&planes[v1.y * PW + w], 1u << ((tl + 1) & 31));
        atomicOr(&planes[v1.z * PW + w], 1u << ((tl + 2) & 31));
        atomicOr(&planes[v1.w * PW + w], 1u << ((tl + 3) & 31));
    }
    __syncthreads();

    // ---- bitsliced accumulation: q = lane-local f-group, blk = position block ----
    const int q   = tid & 7;
    const int blk = tid >> 3;              // 0..15
    unsigned cnt[4];
    switch (q) {                           // fb/NF compile-time per case
        case 0: accum<13>(planes, soff,  0, blk, cnt); break;
        case 1: accum<13>(planes, soff, 13, blk, cnt); break;
        case 2: accum<13>(planes, soff, 26, blk, cnt); break;
        case 3: accum<13>(planes, soff, 39, blk, cnt); break;
        case 4: accum<12>(planes, soff, 52, blk, cnt); break;
        case 5: accum<12>(planes, soff, 64, blk, cnt); break;
        case 6: accum<12>(planes, soff, 76, blk, cnt); break;
        default:accum<12>(planes, soff, 88, blk, cnt); break;
    }

    // ---- in-warp butterfly combine of 8 f-partials (bitsliced adds) ----
    unsigned r[7] = {cnt[0], cnt[1], cnt[2], cnt[3], 0, 0, 0};
    #pragma unroll
    for (int st = 0; st < 3; st++) {
        const int off = 1 << st;
        const int W   = 4 + st;            // planes valid before this stage
        unsigned c = 0;
        #pragma unroll
        for (int k = 0; k < 6; k++) {
            if (k < W) {
                unsigned a = r[k];
                unsigned d = __shfl_xor_sync(0xFFFFFFFFu, a, off);
                r[k] = a ^ d ^ c;
                c    = MAJ(a, d, c);
            }
        }
        r[W] = c;                          // totals: 26 / 52 / 100 -> fits
    }

    // ---- bitplane max over 32 positions + first index (every lane has full sum) ----
    unsigned m = 0xFFFFFFFFu, score = 0;
    #pragma unroll
    for (int k = 6; k >= 0; k--) {
        unsigned t  = m & r[k];
        unsigned nz = (t != 0u);
        m = nz ? t : m;
        score += nz << k;
    }
    const int pos = p0 + blk * 32 + (__ffs(m) - 1);
    unsigned long long key = ((unsigned long long)score << 32)
                           | (unsigned)(0x7FFFFFFF - pos);

    // reduce across the 4 blocks in this warp (8-lane groups already uniform)
    {
        unsigned long long o;
        o = __shfl_xor_sync(0xFFFFFFFFu, key, 8);  if (o > key) key = o;
        o = __shfl_xor_sync(0xFFFFFFFFu, key, 16); if (o > key) key = o;
    }
    if ((tid & 31) == 0) wkey[tid >> 5] = key;
    __syncthreads();

    if (tid == 0) {
        unsigned long long best = wkey[0];
        #pragma unroll
        for (int w = 1; w < NTHREADS / 32; w++)
            if (wkey[w] > best) best = wkey[w];

        atomicMax(&g_key[b], best);
        __threadfence();
        const unsigned arrived = atomicAdd(&g_cnt[b], 1u);
        if (arrived == SEGS - 1) {
            __threadfence();
            const unsigned long long k = atomicMax(&g_key[b], 0ULL);  // atomic read
            out[b]     = (float)(0x7FFFFFFFu - (unsigned)(k & 0xFFFFFFFFu));
            out[B + b] = (float)(unsigned)(k >> 32);
            g_key[b] = 0ULL;               // reset for next graph replay
            g_cnt[b] = 0u;
        }
    }
}

extern "C" void kernel_launch(void* const* d_in, const int* in_sizes, int n_in,
                              void* d_out, int out_size)
{
    const int* expr = (const int*)d_in[0];   // [B, 8192] int32
    const int* sub  = (const int*)d_in[1];   // [B, 100]  int32
    float* out = (float*)d_out;              // [2*B] float32: positions then scores

    const int B = in_sizes[1] / FDIM;        // 64
    dim3 grid(SEGS, B);
    finder_kernel<<<grid, NTHREADS>>>(expr, sub, out, B);
}

// round 6
// speedup vs baseline: 1.4926x; 1.4926x over previous
#include <cuda_runtime.h>

#define LDIM  8192
#define FDIM  100
#define SEG   1024        // positions per CTA
#define SEGS  8
#define BROWS 64
#define PW    40          // words per bitplane (36 used; stride padded)
#define PWZ   36          // words actually used (tokens 0..1151)
#define VP    65          // 64 vocab planes + always-zero plane for PAD
#define NTHREADS 512
#define NG    288         // int4 token groups per CTA (tokens 0..1151)
#define NQ    16          // f-groups (one per warp)

// cross-CTA combine scratch (zero at load; reset by finalizer each launch)
__device__ unsigned long long g_key[BROWS];
__device__ unsigned int       g_cnt[BROWS];

__device__ __forceinline__ unsigned MAJ(unsigned a, unsigned b, unsigned c) {
    return (a & b) | (a & c) | (b & c);       // single LOP3
}

// indicator word for f at position block blk (f compile-time after unroll)
__device__ __forceinline__ unsigned IND(const unsigned* __restrict__ pl,
                                        const int* __restrict__ soff,
                                        int f, int blk)
{
    const unsigned* p = pl + soff[f] + blk + (f >> 5);
    const int r = f & 31;
    return r ? __funnelshift_r(p[0], p[1], r) : p[0];
}

// accumulate NF f's (FB..FB+NF-1), bitsliced over 32 positions; NF<=7 -> 3 planes
template<int FB, int NF>
__device__ __forceinline__ void accum(const unsigned* __restrict__ pl,
                                      const int* __restrict__ soff,
                                      int blk, unsigned cnt[3])
{
    constexpr int H0 = NF / 2, H1 = NF - H0;   // two chains for ILP, each <=4
    unsigned o0 = 0, t0 = 0, q0 = 0;
    unsigned o1 = 0, t1 = 0, q1 = 0;
    #pragma unroll
    for (int j = 0; j < H1; j++) {
        if (j < H0) {
            unsigned x = IND(pl, soff, FB + j, blk);
            unsigned c = o0 & x; o0 ^= x;
            unsigned d = t0 & c; t0 ^= c;
            q0 |= d;
        }
        {
            unsigned x = IND(pl, soff, FB + H0 + j, blk);
            unsigned c = o1 & x; o1 ^= x;
            unsigned d = t1 & c; t1 ^= c;
            q1 |= d;
        }
    }
    // merge two <=4 halves into 3 planes (sum <= 7, no carry out)
    unsigned c0 = o0 & o1;            cnt[0] = o0 ^ o1;
    unsigned c1 = MAJ(t0, t1, c0);    cnt[1] = t0 ^ t1 ^ c0;
    cnt[2] = q0 ^ q1 ^ c1;
}

__global__ __launch_bounds__(NTHREADS)
void finder_kernel(const int* __restrict__ expr,
                   const int* __restrict__ sub,
                   float* __restrict__ out, int B)
{
    __shared__ unsigned planes[VP * PW];          // 10.4 KB bitboards
    __shared__ int soff[FDIM];
    __shared__ unsigned xbuf[NQ - 1][32][3];      // stride 3: conflict-free

    const int s   = blockIdx.x;                   // segment 0..7
    const int b   = blockIdx.y;                   // batch row
    const int tid = threadIdx.x;
    const int p0  = s * SEG;

    // ---- prefetch gmem (overlaps shared zeroing) ----
    const int* erow = expr + b * LDIM;
    int4 v0; bool h0 = false;
    if (tid < NG) {
        const int tg = p0 + 4 * tid;
        if (tg < LDIM) { v0 = *(const int4*)(erow + tg); h0 = true; }
    }
    int sval = 0;
    if (tid < FDIM) sval = sub[b * FDIM + tid];

    // ---- zero bitplanes: 65 planes x 9 uint4 ----
    for (int i = tid; i < VP * (PWZ / 4); i += NTHREADS) {
        const int pl = i / (PWZ / 4), wq = i % (PWZ / 4);
        *(uint4*)&planes[pl * PW + wq * 4] = make_uint4(0, 0, 0, 0);
    }
    if (tid < FDIM) soff[tid] = (sval == 0 ? 64 : sval) * PW;   // PAD -> zero plane
    __syncthreads();

    // ---- scatter bitboard bits (tail tokens beyond L stay 0 == sentinel) ----
    if (h0) {
        const int tl = 4 * tid, w = tl >> 5;
        atomicOr(&planes[v0.x * PW + w], 1u << ((tl    ) & 31));
        atomicOr(&planes[v0.y * PW + w], 1u << ((tl + 1) & 31));
        atomicOr(&planes[v0.z * PW + w], 1u << ((tl + 2) & 31));
        atomicOr(&planes[v0.w * PW + w], 1u << ((tl + 3) & 31));
    }
    __syncthreads();

    // ---- bitsliced accumulation: q = warp (f-group), blk = lane ----
    const int blk = tid & 31;
    const int q   = tid >> 5;                     // warp-uniform
    unsigned cnt[3];
    switch (q) {                                  // groups 0-3: 7 f's; 4-15: 6 f's
        case 0:  accum< 0, 7>(planes, soff, blk, cnt); break;
        case 1:  accum< 7, 7>(planes, soff, blk, cnt); break;
        case 2:  accum<14, 7>(planes, soff, blk, cnt); break;
        case 3:  accum<21, 7>(planes, soff, blk, cnt); break;
        case 4:  accum<28, 6>(planes, soff, blk, cnt); break;
        case 5:  accum<34, 6>(planes, soff, blk, cnt); break;
        case 6:  accum<40, 6>(planes, soff, blk, cnt); break;
        case 7:  accum<46, 6>(planes, soff, blk, cnt); break;
        case 8:  accum<52, 6>(planes, soff, blk, cnt); break;
        case 9:  accum<58, 6>(planes, soff, blk, cnt); break;
        case 10: accum<64, 6>(planes, soff, blk, cnt); break;
        case 11: accum<70, 6>(planes, soff, blk, cnt); break;
        case 12: accum<76, 6>(planes, soff, blk, cnt); break;
        case 13: accum<82, 6>(planes, soff, blk, cnt); break;
        case 14: accum<88, 6>(planes, soff, blk, cnt); break;
        default: accum<94, 6>(planes, soff, blk, cnt); break;
    }
    if (q) {
        xbuf[q - 1][blk][0] = cnt[0];
        xbuf[q - 1][blk][1] = cnt[1];
        xbuf[q - 1][blk][2] = cnt[2];
    }
    __syncthreads();

    if (q == 0) {
        // combine 16 partials: 15 bitsliced 3-plane adds into 7 planes
        unsigned r[7] = {cnt[0], cnt[1], cnt[2], 0, 0, 0, 0};
        #pragma unroll
        for (int pq = 0; pq < NQ - 1; pq++) {
            const unsigned d0 = xbuf[pq][blk][0];
            const unsigned d1 = xbuf[pq][blk][1];
            const unsigned d2 = xbuf[pq][blk][2];
            unsigned a, c;
            a = r[0]; r[0] = a ^ d0;        c = a & d0;
            a = r[1]; r[1] = a ^ d1 ^ c;    c = MAJ(a, d1, c);
            a = r[2]; r[2] = a ^ d2 ^ c;    c = MAJ(a, d2, c);
            a = r[3]; r[3] = a ^ c;         c = a & c;
            a = r[4]; r[4] = a ^ c;         c = a & c;
            a = r[5]; r[5] = a ^ c;         c = a & c;
            r[6] |= c;                      // total <= 100 < 128
        }

        // bitplane max over 32 positions + first index
        unsigned m = 0xFFFFFFFFu, score = 0;
        #pragma unroll
        for (int k = 6; k >= 0; k--) {
            unsigned t  = m & r[k];
            unsigned nz = (t != 0u);
            m = nz ? t : m;
            score += nz << k;
        }
        const int pos = p0 + blk * 32 + (__ffs(m) - 1);
        unsigned long long key = ((unsigned long long)score << 32)
                               | (unsigned)(0x7FFFFFFF - pos);

        #pragma unroll
        for (int off = 16; off; off >>= 1) {
            unsigned long long o = __shfl_xor_sync(0xFFFFFFFFu, key, off);
            if (o > key) key = o;
        }

        if (blk == 0) {
            atomicMax(&g_key[b], key);
            __threadfence();
            const unsigned arrived = atomicAdd(&g_cnt[b], 1u);
            if (arrived == SEGS - 1) {
                __threadfence();
                const unsigned long long k = atomicMax(&g_key[b], 0ULL); // atomic read
                out[b]     = (float)(0x7FFFFFFFu - (unsigned)(k & 0xFFFFFFFFu));
                out[B + b] = (float)(unsigned)(k >> 32);
                g_key[b] = 0ULL;              // reset for next graph replay
                g_cnt[b] = 0u;
            }
        }
    }
}

extern "C" void kernel_launch(void* const* d_in, const int* in_sizes, int n_in,
                              void* d_out, int out_size)
{
    const int* expr = (const int*)d_in[0];   // [B, 8192] int32
    const int* sub  = (const int*)d_in[1];   // [B, 100]  int32
    float* out = (float*)d_out;              // [2*B] float32: positions then scores

    const int B = in_sizes[1] / FDIM;        // 64
    dim3 grid(SEGS, B);
    finder_kernel<<<grid, NTHREADS>>>(expr, sub, out, B);
}